// round 2
// baseline (speedup 1.0000x reference)
#include <cuda_runtime.h>
#include <math.h>

#define BB 256
#define TT 256
#define EE 384
#define HH 6
#define DD 64
#define NHD (HH*DD)           // 384
#define MROWS (BB*TT)         // 65536

// Scratch (device globals — allocation-free rule)
__device__ float g_Q[(size_t)BB*HH*TT*DD];     // [b][h][t][d]
__device__ float g_K[(size_t)BB*HH*TT*DD];
__device__ float g_V[(size_t)BB*HH*TT*DD];
__device__ float g_att[(size_t)BB*TT*NHD];     // [b][s][h*64+d]

// ---------------------------------------------------------------------------
// Kernel 1: fused QKV projection.
// C[m, n] = sum_e x[m, e] * W{q|k|v}[h, e, d],  m = b*T+s, n selects (which,h,d)
// Tiled SGEMM 128x128x16, 256 threads, 8x8 per thread.
// Grid: (512, 9). blockIdx.y: 0-2 -> Q tiles, 3-5 -> K, 6-8 -> V.
// ---------------------------------------------------------------------------
__global__ __launch_bounds__(256) void qkv_gemm_kernel(
    const float* __restrict__ x,
    const float* __restrict__ Wq,
    const float* __restrict__ Wk,
    const float* __restrict__ Wv)
{
    __shared__ float As[16][128];
    __shared__ float Bs[16][128];

    const int tid   = threadIdx.x;
    const int mBase = blockIdx.x * 128;
    const int by    = blockIdx.y;
    const int which = by / 3;
    const int r0    = (by % 3) * 128;     // col offset inside the 384-wide section

    const float* __restrict__ W = (which == 0) ? Wq : (which == 1) ? Wk : Wv;
    float* __restrict__ dst = (which == 0) ? g_Q : (which == 1) ? g_K : g_V;

    const int trow = tid / 16;            // 0..15
    const int tcol = tid % 16;            // 0..15
    const int a_r  = tid >> 1;            // 0..127
    const int a_c  = (tid & 1) * 8;       // 0 or 8
    const int b_c  = tid & 127;           // 0..127
    const int b_r0 = (tid >> 7) * 8;      // 0 or 8
    const int hd   = r0 + b_c;
    const int h    = hd >> 6;
    const int d    = hd & 63;
    const float* __restrict__ wcol = W + (size_t)h * EE * DD + d;  // [e] -> wcol[e*DD]

    float acc[8][8];
#pragma unroll
    for (int i = 0; i < 8; i++)
#pragma unroll
        for (int j = 0; j < 8; j++) acc[i][j] = 0.f;

    for (int k0 = 0; k0 < EE; k0 += 16) {
        // Load A tile (coalesced float4), store transposed As[k][m]
        const float* ap = &x[(size_t)(mBase + a_r) * EE + k0 + a_c];
        float4 av0 = *reinterpret_cast<const float4*>(ap);
        float4 av1 = *reinterpret_cast<const float4*>(ap + 4);
        As[a_c + 0][a_r] = av0.x;  As[a_c + 1][a_r] = av0.y;
        As[a_c + 2][a_r] = av0.z;  As[a_c + 3][a_r] = av0.w;
        As[a_c + 4][a_r] = av1.x;  As[a_c + 5][a_r] = av1.y;
        As[a_c + 6][a_r] = av1.z;  As[a_c + 7][a_r] = av1.w;

        // Load B tile: gather from [H,E,D] weight layout
#pragma unroll
        for (int i = 0; i < 8; i++)
            Bs[b_r0 + i][b_c] = wcol[(size_t)(k0 + b_r0 + i) * DD];

        __syncthreads();

#pragma unroll
        for (int k = 0; k < 16; k++) {
            float4 aa0 = *reinterpret_cast<const float4*>(&As[k][trow * 8]);
            float4 aa1 = *reinterpret_cast<const float4*>(&As[k][trow * 8 + 4]);
            float4 bb0 = *reinterpret_cast<const float4*>(&Bs[k][tcol * 8]);
            float4 bb1 = *reinterpret_cast<const float4*>(&Bs[k][tcol * 8 + 4]);
            float am[8] = {aa0.x, aa0.y, aa0.z, aa0.w, aa1.x, aa1.y, aa1.z, aa1.w};
            float bn[8] = {bb0.x, bb0.y, bb0.z, bb0.w, bb1.x, bb1.y, bb1.z, bb1.w};
#pragma unroll
            for (int i = 0; i < 8; i++)
#pragma unroll
                for (int j = 0; j < 8; j++)
                    acc[i][j] += am[i] * bn[j];
        }
        __syncthreads();
    }

    // Epilogue: scatter into [b][h][t][d] layout
#pragma unroll
    for (int i = 0; i < 8; i++) {
        int m = mBase + trow * 8 + i;
        int b = m >> 8;
        int s = m & 255;
#pragma unroll
        for (int j = 0; j < 8; j += 4) {
            int cn  = tcol * 8 + j;
            int hd2 = r0 + cn;
            int h2  = hd2 >> 6;
            int d2  = hd2 & 63;
            float4 v = make_float4(acc[i][j], acc[i][j+1], acc[i][j+2], acc[i][j+3]);
            *reinterpret_cast<float4*>(
                &dst[(((size_t)b * HH + h2) * TT + s) * DD + d2]) = v;
        }
    }
}

// ---------------------------------------------------------------------------
// Kernel 2: causal attention, one CTA per (b,h).
// K kept transposed [d][t] in smem -> conflict-free LDS.128 along keys.
// Full-row softmax (T=256 fits in smem); unnormalized p, scale at the end.
// ---------------------------------------------------------------------------
#define SMEM_ATTN ((64*256 + 256*64 + 8*256 + 8*64) * 4)   // 141312 bytes

__global__ __launch_bounds__(256) void attn_kernel()
{
    extern __shared__ float sm[];
    float* Kt   = sm;                    // [64][256]
    float* Vs   = sm + 64 * 256;         // [256][64]
    float* sbuf = Vs + 256 * 64;         // [8][256]  per-warp score row
    float* qbuf = sbuf + 8 * 256;        // [8][64]

    const int bh = blockIdx.x;           // b*H + h
    const int b  = bh / HH;
    const int h  = bh % HH;
    const int tid = threadIdx.x;
    const int w  = tid >> 5;
    const int L  = tid & 31;
    const size_t base = (size_t)bh * TT * DD;

    // Stage K (transposed) and V
    for (int idx = tid; idx < TT * (DD / 4); idx += 256) {
        int t = idx >> 4;
        int c = (idx & 15) * 4;
        float4 kv = *reinterpret_cast<const float4*>(&g_K[base + (size_t)t * DD + c]);
        Kt[(c + 0) * TT + t] = kv.x;
        Kt[(c + 1) * TT + t] = kv.y;
        Kt[(c + 2) * TT + t] = kv.z;
        Kt[(c + 3) * TT + t] = kv.w;
        float4 vv = *reinterpret_cast<const float4*>(&g_V[base + (size_t)t * DD + c]);
        *reinterpret_cast<float4*>(&Vs[t * DD + c]) = vv;
    }
    __syncthreads();

    const float scale = 0.125f;          // 1/sqrt(64)
    float* srow = sbuf + w * TT;
    float* qrow = qbuf + w * DD;

    for (int s = w; s < TT; s += 8) {
        // q row -> registers
        qrow[L]      = g_Q[base + (size_t)s * DD + L];
        qrow[L + 32] = g_Q[base + (size_t)s * DD + L + 32];
        __syncwarp();
        float q[64];
#pragma unroll
        for (int dd = 0; dd < 64; dd++) q[dd] = qrow[dd];

        const int nch  = (s >> 7) + 1;   // 128-key chunks covering [0, s]
        const int npad = nch * 128;

        // scores: each lane computes 4 keys per chunk
        for (int c = 0; c < nch; c++) {
            int tbase = c * 128 + L * 4;
            float a0 = 0.f, a1 = 0.f, a2 = 0.f, a3 = 0.f;
#pragma unroll
            for (int dd = 0; dd < 64; dd++) {
                float4 kk = *reinterpret_cast<const float4*>(&Kt[dd * TT + tbase]);
                float qd = q[dd];
                a0 += qd * kk.x; a1 += qd * kk.y; a2 += qd * kk.z; a3 += qd * kk.w;
            }
            float4 sc;
            sc.x = (tbase + 0 <= s) ? a0 * scale : -3.0e38f;
            sc.y = (tbase + 1 <= s) ? a1 * scale : -3.0e38f;
            sc.z = (tbase + 2 <= s) ? a2 * scale : -3.0e38f;
            sc.w = (tbase + 3 <= s) ? a3 * scale : -3.0e38f;
            *reinterpret_cast<float4*>(&srow[tbase]) = sc;
        }
        __syncwarp();

        // softmax (max, exp, sum); keep p unnormalized in srow
        float mx = -3.0e38f;
        for (int t = L; t < npad; t += 32) mx = fmaxf(mx, srow[t]);
#pragma unroll
        for (int o = 16; o; o >>= 1) mx = fmaxf(mx, __shfl_xor_sync(0xffffffffu, mx, o));

        float ssum = 0.f;
        for (int t = L; t < npad; t += 32) {
            float p = __expf(srow[t] - mx);
            srow[t] = p;
            ssum += p;
        }
#pragma unroll
        for (int o = 16; o; o >>= 1) ssum += __shfl_xor_sync(0xffffffffu, ssum, o);
        float inv = 1.0f / ssum;
        __syncwarp();

        // PV: lane owns d = {2L, 2L+1}
        float o0 = 0.f, o1 = 0.f;
        for (int t4 = 0; t4 < npad; t4 += 4) {
            float4 p4 = *reinterpret_cast<const float4*>(&srow[t4]);
            float2 v0 = *reinterpret_cast<const float2*>(&Vs[(t4 + 0) * DD + 2 * L]);
            float2 v1 = *reinterpret_cast<const float2*>(&Vs[(t4 + 1) * DD + 2 * L]);
            float2 v2 = *reinterpret_cast<const float2*>(&Vs[(t4 + 2) * DD + 2 * L]);
            float2 v3 = *reinterpret_cast<const float2*>(&Vs[(t4 + 3) * DD + 2 * L]);
            o0 += p4.x * v0.x + p4.y * v1.x + p4.z * v2.x + p4.w * v3.x;
            o1 += p4.x * v0.y + p4.y * v1.y + p4.z * v2.y + p4.w * v3.y;
        }
        *reinterpret_cast<float2*>(
            &g_att[((size_t)b * TT + s) * NHD + h * DD + 2 * L]) =
            make_float2(o0 * inv, o1 * inv);
        __syncwarp();
    }
}

// ---------------------------------------------------------------------------
// Kernel 3: output projection  out = g_att @ Wo + bo
// Same SGEMM tiling. Grid: (512, 3).
// ---------------------------------------------------------------------------
__global__ __launch_bounds__(256) void out_gemm_kernel(
    const float* __restrict__ Wo,
    const float* __restrict__ bo,
    float* __restrict__ out)
{
    __shared__ float As[16][128];
    __shared__ float Bs[16][128];

    const int tid   = threadIdx.x;
    const int mBase = blockIdx.x * 128;
    const int nBase = blockIdx.y * 128;

    const int trow = tid / 16;
    const int tcol = tid % 16;
    const int a_r  = tid >> 1;
    const int a_c  = (tid & 1) * 8;
    const int b_c  = tid & 127;
    const int b_r0 = (tid >> 7) * 8;

    float acc[8][8];
#pragma unroll
    for (int i = 0; i < 8; i++)
#pragma unroll
        for (int j = 0; j < 8; j++) acc[i][j] = 0.f;

    for (int k0 = 0; k0 < EE; k0 += 16) {
        const float* ap = &g_att[(size_t)(mBase + a_r) * EE + k0 + a_c];
        float4 av0 = *reinterpret_cast<const float4*>(ap);
        float4 av1 = *reinterpret_cast<const float4*>(ap + 4);
        As[a_c + 0][a_r] = av0.x;  As[a_c + 1][a_r] = av0.y;
        As[a_c + 2][a_r] = av0.z;  As[a_c + 3][a_r] = av0.w;
        As[a_c + 4][a_r] = av1.x;  As[a_c + 5][a_r] = av1.y;
        As[a_c + 6][a_r] = av1.z;  As[a_c + 7][a_r] = av1.w;

#pragma unroll
        for (int i = 0; i < 8; i++)
            Bs[b_r0 + i][b_c] = Wo[(size_t)(k0 + b_r0 + i) * EE + nBase + b_c];

        __syncthreads();

#pragma unroll
        for (int k = 0; k < 16; k++) {
            float4 aa0 = *reinterpret_cast<const float4*>(&As[k][trow * 8]);
            float4 aa1 = *reinterpret_cast<const float4*>(&As[k][trow * 8 + 4]);
            float4 bb0 = *reinterpret_cast<const float4*>(&Bs[k][tcol * 8]);
            float4 bb1 = *reinterpret_cast<const float4*>(&Bs[k][tcol * 8 + 4]);
            float am[8] = {aa0.x, aa0.y, aa0.z, aa0.w, aa1.x, aa1.y, aa1.z, aa1.w};
            float bn[8] = {bb0.x, bb0.y, bb0.z, bb0.w, bb1.x, bb1.y, bb1.z, bb1.w};
#pragma unroll
            for (int i = 0; i < 8; i++)
#pragma unroll
                for (int j = 0; j < 8; j++)
                    acc[i][j] += am[i] * bn[j];
        }
        __syncthreads();
    }

#pragma unroll
    for (int i = 0; i < 8; i++) {
        int m = mBase + trow * 8 + i;
#pragma unroll
        for (int j = 0; j < 8; j += 4) {
            int cn = tcol * 8 + j;
            float4 bias = *reinterpret_cast<const float4*>(&bo[nBase + cn]);
            float4 v = make_float4(acc[i][j]   + bias.x,
                                   acc[i][j+1] + bias.y,
                                   acc[i][j+2] + bias.z,
                                   acc[i][j+3] + bias.w);
            *reinterpret_cast<float4*>(&out[(size_t)m * EE + nBase + cn]) = v;
        }
    }
}

// ---------------------------------------------------------------------------
extern "C" void kernel_launch(void* const* d_in, const int* in_sizes, int n_in,
                              void* d_out, int out_size)
{
    const float* x  = (const float*)d_in[0];
    const float* Wq = (const float*)d_in[1];
    const float* Wk = (const float*)d_in[2];
    const float* Wv = (const float*)d_in[3];
    const float* Wo = (const float*)d_in[4];
    const float* bo = (const float*)d_in[5];
    float* out = (float*)d_out;

    cudaFuncSetAttribute(attn_kernel,
                         cudaFuncAttributeMaxDynamicSharedMemorySize, SMEM_ATTN);

    dim3 g1(MROWS / 128, 9);
    qkv_gemm_kernel<<<g1, 256>>>(x, Wq, Wk, Wv);

    attn_kernel<<<BB * HH, 256, SMEM_ATTN>>>();

    dim3 g3(MROWS / 128, 3);
    out_gemm_kernel<<<g3, 256>>>(Wo, bo, out);
}